// round 1
// baseline (speedup 1.0000x reference)
#include <cuda_runtime.h>

#define MAXB 65536
#define SCAN_BLK 256
#define MAXG (MAXB / SCAN_BLK)   // 256

// Scratch (allocation-free): per-batch source/dest starts + scan partials.
__device__ int g_old_start[MAXB];
__device__ int g_new_start[MAXB];
__device__ int g_part_span[MAXG];
__device__ int g_part_filt[MAXG];

// ---------------------------------------------------------------------------
// Pass 1: per-block sums of span = accept_length+1 and filter.
// ---------------------------------------------------------------------------
__global__ void pass1_block_sums(const int* __restrict__ al,
                                 const int* __restrict__ alf, int B) {
    int i = blockIdx.x * SCAN_BLK + threadIdx.x;
    int span = 0, f = 0;
    if (i < B) { span = al[i] + 1; f = alf[i]; }

    // warp reduce
    #pragma unroll
    for (int o = 16; o > 0; o >>= 1) {
        span += __shfl_down_sync(0xffffffffu, span, o);
        f    += __shfl_down_sync(0xffffffffu, f, o);
    }
    __shared__ int ss[SCAN_BLK / 32], sf[SCAN_BLK / 32];
    int w = threadIdx.x >> 5, l = threadIdx.x & 31;
    if (l == 0) { ss[w] = span; sf[w] = f; }
    __syncthreads();
    if (threadIdx.x == 0) {
        int ts = 0, tf = 0;
        #pragma unroll
        for (int k = 0; k < SCAN_BLK / 32; k++) { ts += ss[k]; tf += sf[k]; }
        g_part_span[blockIdx.x] = ts;
        g_part_filt[blockIdx.x] = tf;
    }
}

// ---------------------------------------------------------------------------
// Pass 2: single block, exclusive scan of the <=256 block partials.
// ---------------------------------------------------------------------------
__global__ void pass2_scan_partials(int G) {
    __shared__ int sh[SCAN_BLK];
    int i = threadIdx.x;

    int vs = (i < G) ? g_part_span[i] : 0;
    int vf = (i < G) ? g_part_filt[i] : 0;

    // inclusive Hillis-Steele scan of span partials
    sh[i] = vs; __syncthreads();
    #pragma unroll
    for (int off = 1; off < SCAN_BLK; off <<= 1) {
        int add = (i >= off) ? sh[i - off] : 0;
        __syncthreads();
        sh[i] += add;
        __syncthreads();
    }
    int incl_s = sh[i];
    __syncthreads();

    // inclusive scan of filter partials
    sh[i] = vf; __syncthreads();
    #pragma unroll
    for (int off = 1; off < SCAN_BLK; off <<= 1) {
        int add = (i >= off) ? sh[i - off] : 0;
        __syncthreads();
        sh[i] += add;
        __syncthreads();
    }
    int incl_f = sh[i];

    if (i < G) {
        g_part_span[i] = incl_s - vs;   // exclusive
        g_part_filt[i] = incl_f - vf;
    }
}

// ---------------------------------------------------------------------------
// Pass 3: per-block exclusive scan + block offset -> per-batch starts.
// ---------------------------------------------------------------------------
__global__ void pass3_write_starts(const int* __restrict__ al,
                                   const int* __restrict__ alf, int B) {
    __shared__ int sh[SCAN_BLK];
    int blk = blockIdx.x;
    int i = blk * SCAN_BLK + threadIdx.x;
    int t = threadIdx.x;

    int span = 0, f = 0;
    if (i < B) { span = al[i] + 1; f = alf[i]; }

    // inclusive scan of span within block
    sh[t] = span; __syncthreads();
    #pragma unroll
    for (int off = 1; off < SCAN_BLK; off <<= 1) {
        int add = (t >= off) ? sh[t - off] : 0;
        __syncthreads();
        sh[t] += add;
        __syncthreads();
    }
    int excl_span = sh[t] - span;
    __syncthreads();

    // inclusive scan of filter within block
    sh[t] = f; __syncthreads();
    #pragma unroll
    for (int off = 1; off < SCAN_BLK; off <<= 1) {
        int add = (t >= off) ? sh[t - off] : 0;
        __syncthreads();
        sh[t] += add;
        __syncthreads();
    }
    int excl_f = sh[t] - f;

    if (i < B) {
        g_old_start[i] = g_part_span[blk] + excl_span;
        g_new_start[i] = g_part_filt[blk] + excl_f;
    }
}

// ---------------------------------------------------------------------------
// Copy: one warp per batch, lane-strided.
// ---------------------------------------------------------------------------
__global__ void copy_kernel(const float* __restrict__ src,
                            const int* __restrict__ alf,
                            float* __restrict__ out, int B) {
    int w    = (blockIdx.x * blockDim.x + threadIdx.x) >> 5;
    int lane = threadIdx.x & 31;
    if (w >= B) return;

    int f = alf[w];          // broadcast load (all lanes same addr)
    if (f == 0) return;
    int os = g_old_start[w];
    int ns = g_new_start[w];

    for (int i = lane; i < f; i += 32)
        out[ns + i] = src[os + i];
}

// ---------------------------------------------------------------------------
// Launch
// ---------------------------------------------------------------------------
extern "C" void kernel_launch(void* const* d_in, const int* in_sizes, int n_in,
                              void* d_out, int out_size) {
    const float* tgt_cache_loc = (const float*)d_in[0];
    const int*   accept_length = (const int*)d_in[1];
    const int*   accept_filter = (const int*)d_in[2];
    // d_in[3] = out_size scalar on device; we use the host out_size param.
    (void)n_in; (void)out_size;

    int B = in_sizes[1];
    int G = (B + SCAN_BLK - 1) / SCAN_BLK;

    pass1_block_sums<<<G, SCAN_BLK>>>(accept_length, accept_filter, B);
    pass2_scan_partials<<<1, SCAN_BLK>>>(G);
    pass3_write_starts<<<G, SCAN_BLK>>>(accept_length, accept_filter, B);

    int warps_needed = B;                      // one warp per batch
    int threads = 256;
    int blocks = (warps_needed * 32 + threads - 1) / threads;
    copy_kernel<<<blocks, threads>>>(tgt_cache_loc, accept_filter,
                                     (float*)d_out, B);
}

// round 3
// speedup vs baseline: 1.3385x; 1.3385x over previous
#include <cuda_runtime.h>

#define MAXB 65536
#define SCAN_BLK 256
#define MAXG (MAXB / SCAN_BLK)   // 256

// Scratch (allocation-free): per-batch source/dest starts + scan partials.
__device__ int g_old_start[MAXB];
__device__ int g_new_start[MAXB];
__device__ int g_part_span[MAXG];
__device__ int g_part_filt[MAXG];

// ---------------------------------------------------------------------------
// Pass 1: per-block sums of span = accept_length+1 and filter.
// ---------------------------------------------------------------------------
__global__ void pass1_block_sums(const int* __restrict__ al,
                                 const int* __restrict__ alf, int B) {
    int i = blockIdx.x * SCAN_BLK + threadIdx.x;
    int span = 0, f = 0;
    if (i < B) { span = al[i] + 1; f = alf[i]; }

    #pragma unroll
    for (int o = 16; o > 0; o >>= 1) {
        span += __shfl_down_sync(0xffffffffu, span, o);
        f    += __shfl_down_sync(0xffffffffu, f, o);
    }
    __shared__ int ss[SCAN_BLK / 32], sf[SCAN_BLK / 32];
    int w = threadIdx.x >> 5, l = threadIdx.x & 31;
    if (l == 0) { ss[w] = span; sf[w] = f; }
    __syncthreads();
    if (threadIdx.x == 0) {
        int ts = 0, tf = 0;
        #pragma unroll
        for (int k = 0; k < SCAN_BLK / 32; k++) { ts += ss[k]; tf += sf[k]; }
        g_part_span[blockIdx.x] = ts;
        g_part_filt[blockIdx.x] = tf;
    }
}

// ---------------------------------------------------------------------------
// Pass 2+3 fused: each block redundantly scans the G partials in shared mem
// to get its own block offset, then does the per-element exclusive scan and
// writes per-batch starts.
// ---------------------------------------------------------------------------
__global__ void pass23_write_starts(const int* __restrict__ al,
                                    const int* __restrict__ alf,
                                    int B, int G) {
    __shared__ int sh[SCAN_BLK];
    __shared__ int blk_off_s, blk_off_f;

    int blk = blockIdx.x;
    int t = threadIdx.x;
    int i = blk * SCAN_BLK + t;

    // --- scan the block partials (span), pick exclusive value at blk ---
    int ps = (t < G) ? g_part_span[t] : 0;
    sh[t] = ps; __syncthreads();
    #pragma unroll
    for (int off = 1; off < SCAN_BLK; off <<= 1) {
        int add = (t >= off) ? sh[t - off] : 0;
        __syncthreads();
        sh[t] += add;
        __syncthreads();
    }
    if (t == blk) blk_off_s = sh[t] - ps;   // exclusive prefix at own block
    __syncthreads();

    // --- same for filter partials ---
    int pf = (t < G) ? g_part_filt[t] : 0;
    sh[t] = pf; __syncthreads();
    #pragma unroll
    for (int off = 1; off < SCAN_BLK; off <<= 1) {
        int add = (t >= off) ? sh[t - off] : 0;
        __syncthreads();
        sh[t] += add;
        __syncthreads();
    }
    if (t == blk) blk_off_f = sh[t] - pf;
    __syncthreads();

    // --- per-element scans within this block ---
    int span = 0, f = 0;
    if (i < B) { span = al[i] + 1; f = alf[i]; }

    sh[t] = span; __syncthreads();
    #pragma unroll
    for (int off = 1; off < SCAN_BLK; off <<= 1) {
        int add = (t >= off) ? sh[t - off] : 0;
        __syncthreads();
        sh[t] += add;
        __syncthreads();
    }
    int excl_span = sh[t] - span;
    __syncthreads();

    sh[t] = f; __syncthreads();
    #pragma unroll
    for (int off = 1; off < SCAN_BLK; off <<= 1) {
        int add = (t >= off) ? sh[t - off] : 0;
        __syncthreads();
        sh[t] += add;
        __syncthreads();
    }
    int excl_f = sh[t] - f;

    if (i < B) {
        g_old_start[i] = blk_off_s + excl_span;
        g_new_start[i] = blk_off_f + excl_f;
    }
}

// ---------------------------------------------------------------------------
// Copy: one warp per batch. f <= 512, so 16 lane-strided slots per thread.
// Issue ALL predicated loads first (MLP up to 16), then all stores.
// Streaming hints: data is touched exactly once.
// ---------------------------------------------------------------------------
__global__ void __launch_bounds__(256) copy_kernel(
        const float* __restrict__ src,
        const int* __restrict__ alf,
        float* __restrict__ out, int B) {
    int w    = (blockIdx.x * blockDim.x + threadIdx.x) >> 5;
    int lane = threadIdx.x & 31;
    if (w >= B) return;

    int f = alf[w];          // broadcast load (all lanes same addr)
    if (f == 0) return;
    const float* s = src + g_old_start[w];
    float*       d = out + g_new_start[w];

    // All loads issued back-to-back (independent, predicated) -> high MLP.
    float v[16];
    #pragma unroll
    for (int k = 0; k < 16; k++) {
        int i = lane + k * 32;
        v[k] = (i < f) ? __ldcs(s + i) : 0.0f;
    }
    #pragma unroll
    for (int k = 0; k < 16; k++) {
        int i = lane + k * 32;
        if (i < f) __stcs(d + i, v[k]);
    }
}

// ---------------------------------------------------------------------------
// Launch
// ---------------------------------------------------------------------------
extern "C" void kernel_launch(void* const* d_in, const int* in_sizes, int n_in,
                              void* d_out, int out_size) {
    const float* tgt_cache_loc = (const float*)d_in[0];
    const int*   accept_length = (const int*)d_in[1];
    const int*   accept_filter = (const int*)d_in[2];
    (void)n_in; (void)out_size;

    int B = in_sizes[1];
    int G = (B + SCAN_BLK - 1) / SCAN_BLK;

    pass1_block_sums<<<G, SCAN_BLK>>>(accept_length, accept_filter, B);
    pass23_write_starts<<<G, SCAN_BLK>>>(accept_length, accept_filter, B, G);

    int threads = 256;
    int blocks = (B * 32 + threads - 1) / threads;   // one warp per batch
    copy_kernel<<<blocks, threads>>>(tgt_cache_loc, accept_filter,
                                     (float*)d_out, B);
}

// round 4
// speedup vs baseline: 1.4326x; 1.0702x over previous
#include <cuda_runtime.h>

#define MAXB 65536
#define BLK 256
#define EPT 4                         // elements per thread in scan kernels
#define TILE (BLK * EPT)              // 1024 elements per scan block
#define MAXG (MAXB / TILE)            // 64 partials

// Scratch (allocation-free).
__device__ int4 g_meta[MAXB];                       // {old_start, new_start, f, 0}
__device__ unsigned long long g_part[MAXG + 32];    // per-tile packed sums

__device__ __forceinline__ unsigned long long pack2(int span, int filt) {
    return (unsigned long long)(unsigned int)span |
           ((unsigned long long)(unsigned int)filt << 32);
}

// ---------------------------------------------------------------------------
// Pass 1: per-tile packed sums of (span = al+1, filter).
// grid = ceil(B/1024), block = 256, int4 loads.
// ---------------------------------------------------------------------------
__global__ void __launch_bounds__(BLK) pass1_tile_sums(
        const int* __restrict__ al, const int* __restrict__ alf, int B) {
    int t  = blockIdx.x * BLK + threadIdx.x;
    int i0 = t * EPT;

    unsigned long long p = 0;
    if (i0 + 3 < B) {
        int4 a = *(const int4*)(al + i0);
        int4 f = *(const int4*)(alf + i0);
        p = pack2(a.x + a.y + a.z + a.w + 4, f.x + f.y + f.z + f.w);
    } else {
        for (int i = i0; i < B; i++)
            p += pack2(al[i] + 1, alf[i]);
    }

    #pragma unroll
    for (int o = 16; o > 0; o >>= 1)
        p += __shfl_down_sync(0xffffffffu, p, o);

    __shared__ unsigned long long ws[BLK / 32];
    int lane = threadIdx.x & 31, wid = threadIdx.x >> 5;
    if (lane == 0) ws[wid] = p;
    __syncthreads();
    if (threadIdx.x == 0) {
        unsigned long long tot = 0;
        #pragma unroll
        for (int k = 0; k < BLK / 32; k++) tot += ws[k];
        g_part[blockIdx.x] = tot;
    }
}

// ---------------------------------------------------------------------------
// Pass 2: exclusive scan via warp shuffles; writes per-batch copy metadata.
// grid = ceil(B/1024), block = 256.
// ---------------------------------------------------------------------------
__global__ void __launch_bounds__(BLK) pass2_write_meta(
        const int* __restrict__ al, const int* __restrict__ alf,
        int B, int G) {
    __shared__ unsigned long long warp_excl[BLK / 32];
    __shared__ unsigned long long blk_base_sh;

    int t = threadIdx.x, lane = t & 31, wid = t >> 5;
    int i0 = (blockIdx.x * BLK + t) * EPT;

    // Load and pack 4 elements.
    unsigned long long p[EPT];
    if (i0 + 3 < B) {
        int4 a = *(const int4*)(al + i0);
        int4 f = *(const int4*)(alf + i0);
        p[0] = pack2(a.x + 1, f.x);
        p[1] = pack2(a.y + 1, f.y);
        p[2] = pack2(a.z + 1, f.z);
        p[3] = pack2(a.w + 1, f.w);
    } else {
        #pragma unroll
        for (int k = 0; k < EPT; k++) {
            int i = i0 + k;
            p[k] = (i < B) ? pack2(al[i] + 1, alf[i]) : 0ull;
        }
    }
    unsigned long long tot = p[0] + p[1] + p[2] + p[3];

    // Warp-inclusive scan of per-thread totals.
    unsigned long long incl = tot;
    #pragma unroll
    for (int o = 1; o < 32; o <<= 1) {
        unsigned long long n = __shfl_up_sync(0xffffffffu, incl, o);
        if (lane >= o) incl += n;
    }
    unsigned long long texcl = incl - tot;
    if (lane == 31) warp_excl[wid] = incl;   // warp total (inclusive)
    __syncthreads();

    // Warp 0, lanes 0-7: exclusive scan of the 8 warp totals.
    if (t < BLK / 32) {
        unsigned long long v = warp_excl[t];
        unsigned long long inc = v;
        #pragma unroll
        for (int o = 1; o < BLK / 32; o <<= 1) {
            unsigned long long n = __shfl_up_sync(0xffu, inc, o);
            if (t >= o) inc += n;
        }
        warp_excl[t] = inc - v;
    }
    // Warp 1: block base = sum of g_part[0 .. blockIdx.x).
    if (wid == 1) {
        unsigned long long v = 0;
        for (int j = lane; j < blockIdx.x; j += 32)
            v += g_part[j];
        #pragma unroll
        for (int o = 16; o > 0; o >>= 1)
            v += __shfl_down_sync(0xffffffffu, v, o);
        if (lane == 0) blk_base_sh = v;
    }
    __syncthreads();

    unsigned long long run = blk_base_sh + warp_excl[wid] + texcl;
    #pragma unroll
    for (int k = 0; k < EPT; k++) {
        int i = i0 + k;
        if (i < B) {
            int os = (int)(run & 0xffffffffull);
            int ns = (int)(run >> 32);
            int fv = (int)(p[k] >> 32);
            g_meta[i] = make_int4(os, ns, fv, 0);
            run += p[k];
        }
    }
}

// ---------------------------------------------------------------------------
// Copy: one warp per batch; one LDG.128 metadata broadcast; all <=16
// predicated streaming loads issued before any store (MLP up to 16).
// ---------------------------------------------------------------------------
__global__ void __launch_bounds__(256) copy_kernel(
        const float* __restrict__ src, float* __restrict__ out, int B) {
    int w    = (blockIdx.x * blockDim.x + threadIdx.x) >> 5;
    int lane = threadIdx.x & 31;
    if (w >= B) return;

    int4 m = g_meta[w];          // broadcast: one 128-bit load per warp
    int f = m.z;
    if (f == 0) return;
    const float* s = src + m.x;
    float*       d = out + m.y;

    float v[16];
    #pragma unroll
    for (int k = 0; k < 16; k++) {
        int i = lane + k * 32;
        v[k] = (i < f) ? __ldcs(s + i) : 0.0f;
    }
    #pragma unroll
    for (int k = 0; k < 16; k++) {
        int i = lane + k * 32;
        if (i < f) __stcs(d + i, v[k]);
    }
}

// ---------------------------------------------------------------------------
// Launch
// ---------------------------------------------------------------------------
extern "C" void kernel_launch(void* const* d_in, const int* in_sizes, int n_in,
                              void* d_out, int out_size) {
    const float* tgt_cache_loc = (const float*)d_in[0];
    const int*   accept_length = (const int*)d_in[1];
    const int*   accept_filter = (const int*)d_in[2];
    (void)n_in; (void)out_size;

    int B = in_sizes[1];
    int G = (B + TILE - 1) / TILE;

    pass1_tile_sums<<<G, BLK>>>(accept_length, accept_filter, B);
    pass2_write_meta<<<G, BLK>>>(accept_length, accept_filter, B, G);

    int blocks = (B * 32 + 255) / 256;   // one warp per batch
    copy_kernel<<<blocks, 256>>>(tgt_cache_loc, (float*)d_out, B);
}